// round 15
// baseline (speedup 1.0000x reference)
#include <cuda_runtime.h>
#include <cuda_fp16.h>
#include <cstdint>
#include <math.h>

#define BB 2
#define SS 2048
#define HID 1024
#define NH 16
#define DD 64
#define MM (BB*SS)          // 4096
#define NQT (SS/128)        // 16

// ---------------- scratch (no allocation allowed) ----------------
__device__ __half g_hid[MM*HID];
__device__ __half g_w[4][HID*HID];
__device__ __half g_ctx[MM*HID];

__device__ __half g_qh[MM*HID];
__device__ __half g_kh[MM*HID];
__device__ __half g_v[MM*HID];

// ================= helpers =================
__device__ __forceinline__ uint32_t smem_to_u32(const void* smem_ptr) {
    uint32_t addr;
    asm("{ .reg .u64 tmp; cvta.to.shared.u64 tmp, %1; cvt.u32.u64 %0, tmp; }"
        : "=r"(addr) : "l"(smem_ptr));
    return addr;
}
__device__ __forceinline__ void ldm_x4(uint32_t* r, uint32_t addr) {
    asm volatile("ldmatrix.sync.aligned.m8n8.x4.shared.b16 {%0,%1,%2,%3}, [%4];"
        : "=r"(r[0]), "=r"(r[1]), "=r"(r[2]), "=r"(r[3]) : "r"(addr));
}
__device__ __forceinline__ void ldm_x4_t(uint32_t* r, uint32_t addr) {
    asm volatile("ldmatrix.sync.aligned.m8n8.x4.trans.shared.b16 {%0,%1,%2,%3}, [%4];"
        : "=r"(r[0]), "=r"(r[1]), "=r"(r[2]), "=r"(r[3]) : "r"(addr));
}
__device__ __forceinline__ void mma16816h(float* c, const uint32_t* a, uint32_t b0, uint32_t b1) {
    asm volatile("mma.sync.aligned.m16n8k16.row.col.f32.f16.f16.f32 "
        "{%0,%1,%2,%3}, {%4,%5,%6,%7}, {%8,%9}, {%0,%1,%2,%3};"
        : "+f"(c[0]), "+f"(c[1]), "+f"(c[2]), "+f"(c[3])
        : "r"(a[0]), "r"(a[1]), "r"(a[2]), "r"(a[3]), "r"(b0), "r"(b1));
}
__device__ __forceinline__ void cp16(uint32_t saddr, const void* gaddr) {
    asm volatile("cp.async.cg.shared.global [%0], [%1], 16;" :: "r"(saddr), "l"(gaddr));
}
__device__ __forceinline__ void cp_commit() { asm volatile("cp.async.commit_group;" ::: "memory"); }
__device__ __forceinline__ void cp_wait0() { asm volatile("cp.async.wait_group 0;" ::: "memory"); }
__device__ __forceinline__ void cp_wait1() { asm volatile("cp.async.wait_group 1;" ::: "memory"); }
__device__ __forceinline__ float fexp2(float x) {
    float y; asm("ex2.approx.f32 %0, %1;" : "=f"(y) : "f"(x)); return y;
}

// ================= fp32 -> fp16 convert: hidden + 4 weights in one launch =================
__global__ void convert_all_kernel(const float* __restrict__ hid_f,
                                   const float* __restrict__ w0, const float* __restrict__ w1,
                                   const float* __restrict__ w2, const float* __restrict__ w3,
                                   __half* __restrict__ hid_h, __half* __restrict__ w_h)
{
    const int nh4 = MM * HID / 4;
    const int nw4 = HID * HID / 4;
    int i = blockIdx.x * blockDim.x + threadIdx.x;
    const float* src;
    __half2* dst;
    int j;
    if (i < nh4) {
        src = hid_f; dst = (__half2*)hid_h; j = i;
    } else {
        int t = i - nh4;
        if (t >= 4 * nw4) return;
        int wsel = t / nw4;
        j = t - wsel * nw4;
        src = (wsel == 0) ? w0 : (wsel == 1) ? w1 : (wsel == 2) ? w2 : w3;
        dst = (__half2*)(w_h + (size_t)wsel * HID * HID);
    }
    float4 v = ((const float4*)src)[j];
    dst[j * 2 + 0] = __floats2half2_rn(v.x, v.y);
    dst[j * 2 + 1] = __floats2half2_rn(v.z, v.w);
}

// ================= 128x128-tile fp16 HMMA GEMM (QKV + Wo) =================
// 8 warps (2m x 4n), warp tile 64x32. 2-stage cp.async, 1 barrier/iter.
// mode 0: z0 -> rope+scale -> qout, z1 -> rope -> kout, z2 -> vout (fp16)
// mode 1: fp32 c0 (Wo)
#define WROW 80
#define WT_B (128 * WROW)        // 10240 per operand tile
#define WSTG (2 * WT_B)          // 20480 per stage
#define GNIT (HID / 32)          // 32

__global__ __launch_bounds__(256, 2) void gemm_fp16_kernel(
    const __half* __restrict__ A,
    const __half* __restrict__ W0, const __half* __restrict__ W1,
    const __half* __restrict__ W2,
    const float* __restrict__ cosT, const float* __restrict__ sinT,
    float* __restrict__ c0,
    __half* __restrict__ qout, __half* __restrict__ kout, __half* __restrict__ vout,
    int mode)
{
    __shared__ __align__(16) unsigned char smem[2 * WSTG];   // 40960

    const int tid  = threadIdx.x;
    const int wid  = tid >> 5;
    const int lane = tid & 31;
    const int wm   = wid >> 2;       // 0..1
    const int wn   = wid & 3;        // 0..3
    const int n0   = blockIdx.x * 128;
    const int m0   = blockIdx.y * 128;
    const int z    = blockIdx.z;

    const __half* B = (z == 0) ? W0 : (z == 1) ? W1 : W2;

    const uint32_t sb = smem_to_u32(smem);
    const int rL = tid >> 1;         // 0..127
    const int cL = (tid & 1) * 2;    // chunk base {0,2}

    auto load_stage = [&](int it, int buf) {
        const int k0 = it * 32;
        uint32_t st = sb + buf * WSTG;
#pragma unroll
        for (int j = 0; j < 2; j++) {
            cp16(st + rL * WROW + (cL + j) * 16,
                 A + (size_t)(m0 + rL) * HID + k0 + (cL + j) * 8);
            cp16(st + WT_B + rL * WROW + (cL + j) * 16,
                 B + (size_t)(n0 + rL) * HID + k0 + (cL + j) * 8);
        }
    };

    float acc[4][4][4];
#pragma unroll
    for (int i = 0; i < 4; i++)
#pragma unroll
        for (int j = 0; j < 4; j++)
#pragma unroll
            for (int r = 0; r < 4; r++) acc[i][j][r] = 0.0f;

    const int rowA  = lane & 15;
    const int kofsA = (lane >> 4) * 16;
    const int rowB  = (lane & 7) + ((lane >> 4) & 1) * 8;
    const int kofsB = ((lane >> 3) & 1) * 16;

    load_stage(0, 0);
    cp_commit();

    for (int it = 0; it < GNIT; it++) {
        const int cur = it & 1;
        cp_wait0();
        __syncthreads();
        if (it + 1 < GNIT) { load_stage(it + 1, cur ^ 1); cp_commit(); }

        const uint32_t sA = sb + cur * WSTG;
        const uint32_t sB = sA + WT_B;

#pragma unroll
        for (int kk = 0; kk < 2; kk++) {
            const int kb = kk * 32;
            uint32_t a4[4][4], b8[2][4];
#pragma unroll
            for (int mt = 0; mt < 4; mt++)
                ldm_x4(a4[mt], sA + (wm * 64 + mt * 16 + rowA) * WROW + kb + kofsA);
#pragma unroll
            for (int nt2 = 0; nt2 < 2; nt2++)
                ldm_x4(b8[nt2], sB + (wn * 32 + nt2 * 16 + rowB) * WROW + kb + kofsB);
#pragma unroll
            for (int mt = 0; mt < 4; mt++)
#pragma unroll
                for (int nt2 = 0; nt2 < 2; nt2++) {
                    mma16816h(acc[mt][2 * nt2],     a4[mt], b8[nt2][0], b8[nt2][1]);
                    mma16816h(acc[mt][2 * nt2 + 1], a4[mt], b8[nt2][2], b8[nt2][3]);
                }
        }
        // single barrier per iteration: next iteration's top barrier orders buffer reuse
    }

    const int rr = lane >> 2;
    const int cc = (lane & 3) * 2;

    if (mode == 1) {
#pragma unroll
        for (int mt = 0; mt < 4; mt++)
#pragma unroll
            for (int nt = 0; nt < 4; nt++) {
                int r = m0 + wm * 64 + mt * 16 + rr;
                int c = n0 + wn * 32 + nt * 8 + cc;
                *(float2*)&c0[(size_t)r * HID + c] =
                    make_float2(acc[mt][nt][0], acc[mt][nt][1]);
                *(float2*)&c0[(size_t)(r + 8) * HID + c] =
                    make_float2(acc[mt][nt][2], acc[mt][nt][3]);
            }
        return;
    }

    if (z == 2) {
#pragma unroll
        for (int mt = 0; mt < 4; mt++)
#pragma unroll
            for (int nt = 0; nt < 4; nt++) {
                int r = m0 + wm * 64 + mt * 16 + rr;
                int c = n0 + wn * 32 + nt * 8 + cc;
#pragma unroll
                for (int half_ = 0; half_ < 2; half_++) {
                    size_t idx = (size_t)(r + half_ * 8) * HID + c;
                    *(__half2*)&vout[idx] =
                        __floats2half2_rn(acc[mt][nt][half_ * 2], acc[mt][nt][half_ * 2 + 1]);
                }
            }
    } else {
        __half* dst = (z == 0) ? qout : kout;
        const float scale = (z == 0) ? 0.125f * 1.4426950408889634f : 1.0f;
#pragma unroll
        for (int mt = 0; mt < 4; mt++)
#pragma unroll
            for (int nt = 0; nt < 4; nt++) {
                int c = n0 + wn * 32 + nt * 8 + cc;      // even
                int p = (c & 63) >> 1;
#pragma unroll
                for (int half_ = 0; half_ < 2; half_++) {
                    int r = m0 + wm * 64 + mt * 16 + rr + half_ * 8;
                    int s = r & (SS - 1);
                    float co = cosT[s * 32 + p];
                    float si = sinT[s * 32 + p];
                    float a = acc[mt][nt][half_ * 2];
                    float b = acc[mt][nt][half_ * 2 + 1];
                    float o0 = (a * co - b * si) * scale;
                    float o1 = (a * si + b * co) * scale;
                    *(__half2*)&dst[(size_t)r * HID + c] = __floats2half2_rn(o0, o1);
                }
            }
    }
}

// ---------------- fp16 HMMA flash attention (causal, qi-paired) — unchanged ----------------
#define ASTR 144
#define AQB  (128 * ASTR)
#define AKB  (64 * ASTR)
#define AKVSTG (2 * AKB)
#define ATTN_SMEM (AQB + 2 * AKVSTG)   // 55296

__global__ __launch_bounds__(256, 2) void attn_hmma_kernel(
    const __half* __restrict__ qh, const __half* __restrict__ kh,
    const __half* __restrict__ vv,
    __half* __restrict__ ctxh)
{
    extern __shared__ unsigned char sm[];
    const int pid = blockIdx.x;
    const int h   = blockIdx.y;
    const int b   = blockIdx.z;
    const int tid = threadIdx.x;
    const int wid = tid >> 5;
    const int lane = tid & 31;

    const uint32_t sb  = smem_to_u32(sm);
    const uint32_t sQh = sb;
    const uint32_t sKV = sb + AQB;

    const int rowA  = lane & 15;
    const int kofsA = (lane >> 4) * 16;
    const int rowB  = (lane & 7) + ((lane >> 4) & 1) * 8;
    const int kofsB = ((lane >> 3) & 1) * 16;

#pragma unroll 1
    for (int phase = 0; phase < 2; phase++) {
        const int qi = (phase == 0) ? (NQT - 1 - pid) : pid;
        const int q0 = qi * 128;
        const int ntiles = 2 * qi + 2;

        if (phase) __syncthreads();

        {
            int row = tid >> 1;
            int c   = (tid & 1) * 4;
            size_t g = ((size_t)(b * SS + q0 + row) * NH + h) * DD;
#pragma unroll
            for (int j = 0; j < 4; j++)
                cp16(sQh + row * ASTR + (c + j) * 16, qh + g + (c + j) * 8);
        }
        auto loadKV = [&](int jt, int buf) {
            uint32_t base = sKV + buf * AKVSTG;
            int row = tid >> 2;
            int c   = (tid & 3) * 2;
            size_t g = ((size_t)(b * SS + jt * 64 + row) * NH + h) * DD;
#pragma unroll
            for (int j = 0; j < 2; j++) {
                uint32_t so = row * ASTR + (c + j) * 16;
                size_t go = g + (c + j) * 8;
                cp16(base + so,       kh + go);
                cp16(base + AKB + so, vv + go);
            }
        };
        loadKV(0, 0);
        cp_commit();
        loadKV(1, 1);
        cp_commit();
        cp_wait1();
        __syncthreads();

        float mrow[2] = {-1e30f, -1e30f};
        float lrow[2] = {0.0f, 0.0f};
        float oacc[8][4];
#pragma unroll
        for (int nt = 0; nt < 8; nt++)
#pragma unroll
            for (int r = 0; r < 4; r++) oacc[nt][r] = 0.0f;

        for (int jt = 0; jt < ntiles; jt++) {
            const int cur = jt & 1;
            const uint32_t bK = sKV + cur * AKVSTG;
            const uint32_t bV = bK + AKB;
            const int kv0 = jt * 64;
            const int qtop = q0 + wid * 16 + 15;

            if (kv0 <= qtop) {
                float sc[8][4];
#pragma unroll
                for (int nt = 0; nt < 8; nt++)
#pragma unroll
                    for (int r = 0; r < 4; r++) sc[nt][r] = 0.0f;

#pragma unroll
                for (int ks = 0; ks < 4; ks++) {
                    uint32_t ah[4];
                    ldm_x4(ah, sQh + (wid * 16 + rowA) * ASTR + ks * 32 + kofsA);
#pragma unroll
                    for (int nt2 = 0; nt2 < 4; nt2++) {
                        uint32_t b4[4];
                        ldm_x4(b4, bK + (nt2 * 16 + rowB) * ASTR + ks * 32 + kofsB);
                        mma16816h(sc[2 * nt2],     ah, b4[0], b4[1]);
                        mma16816h(sc[2 * nt2 + 1], ah, b4[2], b4[3]);
                    }
                }

                if (kv0 + 63 > q0 + wid * 16) {
                    const int qr = q0 + wid * 16 + (lane >> 2);
#pragma unroll
                    for (int nt = 0; nt < 8; nt++) {
#pragma unroll
                        for (int r = 0; r < 4; r++) {
                            int qrow = qr + ((r >= 2) ? 8 : 0);
                            int kvc  = kv0 + nt * 8 + (lane & 3) * 2 + (r & 1);
                            if (kvc > qrow) sc[nt][r] = -1e30f;
                        }
                    }
                }

#pragma unroll
                for (int rh = 0; rh < 2; rh++) {
                    float mx = -1e30f;
#pragma unroll
                    for (int nt = 0; nt < 8; nt++)
                        mx = fmaxf(mx, fmaxf(sc[nt][rh * 2], sc[nt][rh * 2 + 1]));
                    mx = fmaxf(mx, __shfl_xor_sync(0xffffffffu, mx, 1));
                    mx = fmaxf(mx, __shfl_xor_sync(0xffffffffu, mx, 2));
                    float mn = fmaxf(mrow[rh], mx);
                    float alpha = fexp2(mrow[rh] - mn);
                    mrow[rh] = mn;
                    float sum = 0.0f;
#pragma unroll
                    for (int nt = 0; nt < 8; nt++) {
                        float p0 = fexp2(sc[nt][rh * 2]     - mn);
                        float p1 = fexp2(sc[nt][rh * 2 + 1] - mn);
                        sc[nt][rh * 2]     = p0;
                        sc[nt][rh * 2 + 1] = p1;
                        sum += p0 + p1;
                    }
                    sum += __shfl_xor_sync(0xffffffffu, sum, 1);
                    sum += __shfl_xor_sync(0xffffffffu, sum, 2);
                    lrow[rh] = lrow[rh] * alpha + sum;
#pragma unroll
                    for (int nt = 0; nt < 8; nt++) {
                        oacc[nt][rh * 2]     *= alpha;
                        oacc[nt][rh * 2 + 1] *= alpha;
                    }
                }

                uint32_t ph[4][4];
#pragma unroll
                for (int ks2 = 0; ks2 < 4; ks2++) {
                    const int na = 2 * ks2, nb = 2 * ks2 + 1;
                    __half2 t0 = __floats2half2_rn(sc[na][0], sc[na][1]);
                    __half2 t1 = __floats2half2_rn(sc[na][2], sc[na][3]);
                    __half2 t2 = __floats2half2_rn(sc[nb][0], sc[nb][1]);
                    __half2 t3 = __floats2half2_rn(sc[nb][2], sc[nb][3]);
                    ph[ks2][0] = *(uint32_t*)&t0;
                    ph[ks2][1] = *(uint32_t*)&t1;
                    ph[ks2][2] = *(uint32_t*)&t2;
                    ph[ks2][3] = *(uint32_t*)&t3;
                }

#pragma unroll
                for (int ks2 = 0; ks2 < 4; ks2++) {
#pragma unroll
                    for (int nt2 = 0; nt2 < 4; nt2++) {
                        uint32_t bv[4];
                        uint32_t voff = (ks2 * 16 + (lane & 15)) * ASTR + (nt2 * 16 + (lane >> 4) * 8) * 2;
                        ldm_x4_t(bv, bV + voff);
                        mma16816h(oacc[2 * nt2],     ph[ks2], bv[0], bv[1]);
                        mma16816h(oacc[2 * nt2 + 1], ph[ks2], bv[2], bv[3]);
                    }
                }
            }

            if (jt + 1 < ntiles) {
                __syncthreads();
                if (jt + 2 < ntiles) { loadKV(jt + 2, cur); cp_commit(); cp_wait1(); }
                else cp_wait0();
                __syncthreads();
            }
        }

#pragma unroll
        for (int rh = 0; rh < 2; rh++) {
            float inv = 1.0f / lrow[rh];
            int row = q0 + wid * 16 + (lane >> 2) + rh * 8;
            size_t base = ((size_t)(b * SS + row) * NH + h) * DD;
#pragma unroll
            for (int nt = 0; nt < 8; nt++) {
                float x0 = oacc[nt][rh * 2] * inv;
                float x1 = oacc[nt][rh * 2 + 1] * inv;
                *(__half2*)&ctxh[base + nt * 8 + (lane & 3) * 2] = __floats2half2_rn(x0, x1);
            }
        }
    }
}

// ---------------- host ----------------
extern "C" void kernel_launch(void* const* d_in, const int* in_sizes, int n_in,
                              void* d_out, int out_size)
{
    const float* hidden = (const float*)d_in[0];
    const float* cosT   = (const float*)d_in[1];
    const float* sinT   = (const float*)d_in[2];
    const float* Wq = (const float*)d_in[4];
    const float* Wk = (const float*)d_in[5];
    const float* Wv = (const float*)d_in[6];
    const float* Wo = (const float*)d_in[7];
    float* out = (float*)d_out;

    __half *hid, *w, *ctx, *qh, *kh, *v;
    cudaGetSymbolAddress((void**)&hid, g_hid);
    cudaGetSymbolAddress((void**)&w,   g_w);
    cudaGetSymbolAddress((void**)&ctx, g_ctx);
    cudaGetSymbolAddress((void**)&qh, g_qh);
    cudaGetSymbolAddress((void**)&kh, g_kh);
    cudaGetSymbolAddress((void**)&v,  g_v);

    int ncv = MM * HID / 4 + 4 * (HID * HID / 4);
    convert_all_kernel<<<(ncv + 255) / 256, 256>>>(hidden, Wq, Wk, Wv, Wo, hid, w);

    // QKV projections: 128x128 tiles, grid (8, 32, 3)
    gemm_fp16_kernel<<<dim3(8, 32, 3), 256>>>(
        hid,
        w + 0 * (size_t)HID * HID, w + 1 * (size_t)HID * HID, w + 2 * (size_t)HID * HID,
        cosT, sinT,
        (float*)0, qh, kh, v, /*mode=*/0);

    cudaFuncSetAttribute(attn_hmma_kernel, cudaFuncAttributeMaxDynamicSharedMemorySize, ATTN_SMEM);
    dim3 aGrid(NQT / 2, NH, BB);
    attn_hmma_kernel<<<aGrid, 256, ATTN_SMEM>>>(qh, kh, v, ctx);

    // Wo projection: same kernel, mode 1, grid (8, 32, 1)
    gemm_fp16_kernel<<<dim3(8, 32, 1), 256>>>(
        ctx,
        w + 3 * (size_t)HID * HID, (const __half*)0, (const __half*)0,
        cosT, sinT,
        out, (__half*)0, (__half*)0, (__half*)0, /*mode=*/1);
}

// round 16
// speedup vs baseline: 1.5287x; 1.5287x over previous
#include <cuda_runtime.h>
#include <cuda_fp16.h>
#include <cstdint>
#include <math.h>

#define BB 2
#define SS 2048
#define HID 1024
#define NH 16
#define DD 64
#define MM (BB*SS)          // 4096
#define NQT (SS/128)        // 16

// ---------------- scratch (no allocation allowed) ----------------
__device__ __half g_hid[MM*HID];
__device__ __half g_w[4][HID*HID];
__device__ __half g_ctx[MM*HID];

__device__ __half g_qh[MM*HID];
__device__ __half g_kh[MM*HID];
__device__ __half g_v[MM*HID];

// ================= helpers =================
__device__ __forceinline__ uint32_t smem_to_u32(const void* smem_ptr) {
    uint32_t addr;
    asm("{ .reg .u64 tmp; cvta.to.shared.u64 tmp, %1; cvt.u32.u64 %0, tmp; }"
        : "=r"(addr) : "l"(smem_ptr));
    return addr;
}
__device__ __forceinline__ void ldm_x4(uint32_t* r, uint32_t addr) {
    asm volatile("ldmatrix.sync.aligned.m8n8.x4.shared.b16 {%0,%1,%2,%3}, [%4];"
        : "=r"(r[0]), "=r"(r[1]), "=r"(r[2]), "=r"(r[3]) : "r"(addr));
}
__device__ __forceinline__ void ldm_x4_t(uint32_t* r, uint32_t addr) {
    asm volatile("ldmatrix.sync.aligned.m8n8.x4.trans.shared.b16 {%0,%1,%2,%3}, [%4];"
        : "=r"(r[0]), "=r"(r[1]), "=r"(r[2]), "=r"(r[3]) : "r"(addr));
}
__device__ __forceinline__ void mma16816h(float* c, const uint32_t* a, uint32_t b0, uint32_t b1) {
    asm volatile("mma.sync.aligned.m16n8k16.row.col.f32.f16.f16.f32 "
        "{%0,%1,%2,%3}, {%4,%5,%6,%7}, {%8,%9}, {%0,%1,%2,%3};"
        : "+f"(c[0]), "+f"(c[1]), "+f"(c[2]), "+f"(c[3])
        : "r"(a[0]), "r"(a[1]), "r"(a[2]), "r"(a[3]), "r"(b0), "r"(b1));
}
__device__ __forceinline__ void cp16(uint32_t saddr, const void* gaddr) {
    asm volatile("cp.async.cg.shared.global [%0], [%1], 16;" :: "r"(saddr), "l"(gaddr));
}
__device__ __forceinline__ void cp_commit() { asm volatile("cp.async.commit_group;" ::: "memory"); }
__device__ __forceinline__ void cp_wait0() { asm volatile("cp.async.wait_group 0;" ::: "memory"); }
__device__ __forceinline__ void cp_wait1() { asm volatile("cp.async.wait_group 1;" ::: "memory"); }
__device__ __forceinline__ float fexp2(float x) {
    float y; asm("ex2.approx.f32 %0, %1;" : "=f"(y) : "f"(x)); return y;
}

// ================= fp32 -> fp16 convert: hidden + 4 weights in one launch =================
__global__ void convert_all_kernel(const float* __restrict__ hid_f,
                                   const float* __restrict__ w0, const float* __restrict__ w1,
                                   const float* __restrict__ w2, const float* __restrict__ w3,
                                   __half* __restrict__ hid_h, __half* __restrict__ w_h)
{
    const int nh4 = MM * HID / 4;
    const int nw4 = HID * HID / 4;
    int i = blockIdx.x * blockDim.x + threadIdx.x;
    const float* src;
    __half2* dst;
    int j;
    if (i < nh4) {
        src = hid_f; dst = (__half2*)hid_h; j = i;
    } else {
        int t = i - nh4;
        if (t >= 4 * nw4) return;
        int wsel = t / nw4;
        j = t - wsel * nw4;
        src = (wsel == 0) ? w0 : (wsel == 1) ? w1 : (wsel == 2) ? w2 : w3;
        dst = (__half2*)(w_h + (size_t)wsel * HID * HID);
    }
    float4 v = ((const float4*)src)[j];
    dst[j * 2 + 0] = __floats2half2_rn(v.x, v.y);
    dst[j * 2 + 1] = __floats2half2_rn(v.z, v.w);
}

// ================= shared GEMM config (128x128 tile) =================
#define WROW 80
#define WT_B (128 * WROW)        // 10240 per operand tile
#define WSTG (2 * WT_B)          // 20480 per stage
#define GNIT (HID / 32)          // 32

// ================= QKV GEMM: dedicated 128x128 kernel with RoPE/V epilogue =================
__global__ __launch_bounds__(256, 2) void gemm_qkv_kernel(
    const __half* __restrict__ A,
    const __half* __restrict__ W0, const __half* __restrict__ W1,
    const __half* __restrict__ W2,
    const float* __restrict__ cosT, const float* __restrict__ sinT,
    __half* __restrict__ qout, __half* __restrict__ kout, __half* __restrict__ vout)
{
    __shared__ __align__(16) unsigned char smem[2 * WSTG];   // 40960

    const int tid  = threadIdx.x;
    const int wid  = tid >> 5;
    const int lane = tid & 31;
    const int wm   = wid >> 2;       // 0..1
    const int wn   = wid & 3;        // 0..3
    const int n0   = blockIdx.x * 128;
    const int m0   = blockIdx.y * 128;
    const int z    = blockIdx.z;

    const __half* B = (z == 0) ? W0 : (z == 1) ? W1 : W2;

    const uint32_t sb = smem_to_u32(smem);
    const int rL = tid >> 1;         // 0..127
    const int cL = (tid & 1) * 2;    // chunk base {0,2}

    auto load_stage = [&](int it, int buf) {
        const int k0 = it * 32;
        uint32_t st = sb + buf * WSTG;
#pragma unroll
        for (int j = 0; j < 2; j++) {
            cp16(st + rL * WROW + (cL + j) * 16,
                 A + (size_t)(m0 + rL) * HID + k0 + (cL + j) * 8);
            cp16(st + WT_B + rL * WROW + (cL + j) * 16,
                 B + (size_t)(n0 + rL) * HID + k0 + (cL + j) * 8);
        }
    };

    float acc[4][4][4];
#pragma unroll
    for (int i = 0; i < 4; i++)
#pragma unroll
        for (int j = 0; j < 4; j++)
#pragma unroll
            for (int r = 0; r < 4; r++) acc[i][j][r] = 0.0f;

    const int rowA  = lane & 15;
    const int kofsA = (lane >> 4) * 16;
    const int rowB  = (lane & 7) + ((lane >> 4) & 1) * 8;
    const int kofsB = ((lane >> 3) & 1) * 16;

    load_stage(0, 0);
    cp_commit();

    for (int it = 0; it < GNIT; it++) {
        const int cur = it & 1;
        cp_wait0();
        __syncthreads();
        if (it + 1 < GNIT) { load_stage(it + 1, cur ^ 1); cp_commit(); }

        const uint32_t sA = sb + cur * WSTG;
        const uint32_t sB = sA + WT_B;

#pragma unroll
        for (int kk = 0; kk < 2; kk++) {
            const int kb = kk * 32;
            uint32_t a4[4][4], b8[2][4];
#pragma unroll
            for (int mt = 0; mt < 4; mt++)
                ldm_x4(a4[mt], sA + (wm * 64 + mt * 16 + rowA) * WROW + kb + kofsA);
#pragma unroll
            for (int nt2 = 0; nt2 < 2; nt2++)
                ldm_x4(b8[nt2], sB + (wn * 32 + nt2 * 16 + rowB) * WROW + kb + kofsB);
#pragma unroll
            for (int mt = 0; mt < 4; mt++)
#pragma unroll
                for (int nt2 = 0; nt2 < 2; nt2++) {
                    mma16816h(acc[mt][2 * nt2],     a4[mt], b8[nt2][0], b8[nt2][1]);
                    mma16816h(acc[mt][2 * nt2 + 1], a4[mt], b8[nt2][2], b8[nt2][3]);
                }
        }
        // single barrier per iteration: next iteration's top barrier orders buffer reuse
    }

    const int rr = lane >> 2;
    const int cc = (lane & 3) * 2;

    if (z == 2) {
#pragma unroll
        for (int mt = 0; mt < 4; mt++)
#pragma unroll
            for (int nt = 0; nt < 4; nt++) {
                int r = m0 + wm * 64 + mt * 16 + rr;
                int c = n0 + wn * 32 + nt * 8 + cc;
#pragma unroll
                for (int half_ = 0; half_ < 2; half_++) {
                    size_t idx = (size_t)(r + half_ * 8) * HID + c;
                    *(__half2*)&vout[idx] =
                        __floats2half2_rn(acc[mt][nt][half_ * 2], acc[mt][nt][half_ * 2 + 1]);
                }
            }
    } else {
        __half* dst = (z == 0) ? qout : kout;
        const float scale = (z == 0) ? 0.125f * 1.4426950408889634f : 1.0f;
#pragma unroll
        for (int mt = 0; mt < 4; mt++)
#pragma unroll
            for (int nt = 0; nt < 4; nt++) {
                int c = n0 + wn * 32 + nt * 8 + cc;      // even
                int p = (c & 63) >> 1;
#pragma unroll
                for (int half_ = 0; half_ < 2; half_++) {
                    int r = m0 + wm * 64 + mt * 16 + rr + half_ * 8;
                    int s = r & (SS - 1);
                    float co = cosT[s * 32 + p];
                    float si = sinT[s * 32 + p];
                    float a = acc[mt][nt][half_ * 2];
                    float b = acc[mt][nt][half_ * 2 + 1];
                    float o0 = (a * co - b * si) * scale;
                    float o1 = (a * si + b * co) * scale;
                    *(__half2*)&dst[(size_t)r * HID + c] = __floats2half2_rn(o0, o1);
                }
            }
    }
}

// ================= Wo GEMM: dedicated 128x128 kernel (R13, proven) =================
__global__ __launch_bounds__(256, 2) void gemm_wo_kernel(
    const __half* __restrict__ A, const __half* __restrict__ W,
    float* __restrict__ C)
{
    __shared__ __align__(16) unsigned char smem[2 * WSTG];

    const int tid  = threadIdx.x;
    const int wid  = tid >> 5;
    const int lane = tid & 31;
    const int wm   = wid >> 2;
    const int wn   = wid & 3;
    const int n0   = blockIdx.x * 128;
    const int m0   = blockIdx.y * 128;

    const uint32_t sb = smem_to_u32(smem);
    const int rL = tid >> 1;
    const int cL = (tid & 1) * 2;

    auto load_stage = [&](int it, int buf) {
        const int k0 = it * 32;
        uint32_t st = sb + buf * WSTG;
#pragma unroll
        for (int j = 0; j < 2; j++) {
            cp16(st + rL * WROW + (cL + j) * 16,
                 A + (size_t)(m0 + rL) * HID + k0 + (cL + j) * 8);
            cp16(st + WT_B + rL * WROW + (cL + j) * 16,
                 W + (size_t)(n0 + rL) * HID + k0 + (cL + j) * 8);
        }
    };

    float acc[4][4][4];
#pragma unroll
    for (int i = 0; i < 4; i++)
#pragma unroll
        for (int j = 0; j < 4; j++)
#pragma unroll
            for (int r = 0; r < 4; r++) acc[i][j][r] = 0.0f;

    const int rowA  = lane & 15;
    const int kofsA = (lane >> 4) * 16;
    const int rowB  = (lane & 7) + ((lane >> 4) & 1) * 8;
    const int kofsB = ((lane >> 3) & 1) * 16;

    load_stage(0, 0);
    cp_commit();

    for (int it = 0; it < GNIT; it++) {
        const int cur = it & 1;
        cp_wait0();
        __syncthreads();
        if (it + 1 < GNIT) { load_stage(it + 1, cur ^ 1); cp_commit(); }

        const uint32_t sA = sb + cur * WSTG;
        const uint32_t sB = sA + WT_B;

#pragma unroll
        for (int kk = 0; kk < 2; kk++) {
            const int kb = kk * 32;
            uint32_t a4[4][4], b8[2][4];
#pragma unroll
            for (int mt = 0; mt < 4; mt++)
                ldm_x4(a4[mt], sA + (wm * 64 + mt * 16 + rowA) * WROW + kb + kofsA);
#pragma unroll
            for (int nt2 = 0; nt2 < 2; nt2++)
                ldm_x4(b8[nt2], sB + (wn * 32 + nt2 * 16 + rowB) * WROW + kb + kofsB);
#pragma unroll
            for (int mt = 0; mt < 4; mt++)
#pragma unroll
                for (int nt2 = 0; nt2 < 2; nt2++) {
                    mma16816h(acc[mt][2 * nt2],     a4[mt], b8[nt2][0], b8[nt2][1]);
                    mma16816h(acc[mt][2 * nt2 + 1], a4[mt], b8[nt2][2], b8[nt2][3]);
                }
        }
    }

    const int rr = lane >> 2;
    const int cc = (lane & 3) * 2;
#pragma unroll
    for (int mt = 0; mt < 4; mt++)
#pragma unroll
        for (int nt = 0; nt < 4; nt++) {
            int r = m0 + wm * 64 + mt * 16 + rr;
            int c = n0 + wn * 32 + nt * 8 + cc;
            *(float2*)&C[(size_t)r * HID + c] =
                make_float2(acc[mt][nt][0], acc[mt][nt][1]);
            *(float2*)&C[(size_t)(r + 8) * HID + c] =
                make_float2(acc[mt][nt][2], acc[mt][nt][3]);
        }
}

// ---------------- fp16 HMMA flash attention (causal, qi-paired) — unchanged ----------------
#define ASTR 144
#define AQB  (128 * ASTR)
#define AKB  (64 * ASTR)
#define AKVSTG (2 * AKB)
#define ATTN_SMEM (AQB + 2 * AKVSTG)   // 55296

__global__ __launch_bounds__(256, 2) void attn_hmma_kernel(
    const __half* __restrict__ qh, const __half* __restrict__ kh,
    const __half* __restrict__ vv,
    __half* __restrict__ ctxh)
{
    extern __shared__ unsigned char sm[];
    const int pid = blockIdx.x;
    const int h   = blockIdx.y;
    const int b   = blockIdx.z;
    const int tid = threadIdx.x;
    const int wid = tid >> 5;
    const int lane = tid & 31;

    const uint32_t sb  = smem_to_u32(sm);
    const uint32_t sQh = sb;
    const uint32_t sKV = sb + AQB;

    const int rowA  = lane & 15;
    const int kofsA = (lane >> 4) * 16;
    const int rowB  = (lane & 7) + ((lane >> 4) & 1) * 8;
    const int kofsB = ((lane >> 3) & 1) * 16;

#pragma unroll 1
    for (int phase = 0; phase < 2; phase++) {
        const int qi = (phase == 0) ? (NQT - 1 - pid) : pid;
        const int q0 = qi * 128;
        const int ntiles = 2 * qi + 2;

        if (phase) __syncthreads();

        {
            int row = tid >> 1;
            int c   = (tid & 1) * 4;
            size_t g = ((size_t)(b * SS + q0 + row) * NH + h) * DD;
#pragma unroll
            for (int j = 0; j < 4; j++)
                cp16(sQh + row * ASTR + (c + j) * 16, qh + g + (c + j) * 8);
        }
        auto loadKV = [&](int jt, int buf) {
            uint32_t base = sKV + buf * AKVSTG;
            int row = tid >> 2;
            int c   = (tid & 3) * 2;
            size_t g = ((size_t)(b * SS + jt * 64 + row) * NH + h) * DD;
#pragma unroll
            for (int j = 0; j < 2; j++) {
                uint32_t so = row * ASTR + (c + j) * 16;
                size_t go = g + (c + j) * 8;
                cp16(base + so,       kh + go);
                cp16(base + AKB + so, vv + go);
            }
        };
        loadKV(0, 0);
        cp_commit();
        loadKV(1, 1);
        cp_commit();
        cp_wait1();
        __syncthreads();

        float mrow[2] = {-1e30f, -1e30f};
        float lrow[2] = {0.0f, 0.0f};
        float oacc[8][4];
#pragma unroll
        for (int nt = 0; nt < 8; nt++)
#pragma unroll
            for (int r = 0; r < 4; r++) oacc[nt][r] = 0.0f;

        for (int jt = 0; jt < ntiles; jt++) {
            const int cur = jt & 1;
            const uint32_t bK = sKV + cur * AKVSTG;
            const uint32_t bV = bK + AKB;
            const int kv0 = jt * 64;
            const int qtop = q0 + wid * 16 + 15;

            if (kv0 <= qtop) {
                float sc[8][4];
#pragma unroll
                for (int nt = 0; nt < 8; nt++)
#pragma unroll
                    for (int r = 0; r < 4; r++) sc[nt][r] = 0.0f;

#pragma unroll
                for (int ks = 0; ks < 4; ks++) {
                    uint32_t ah[4];
                    ldm_x4(ah, sQh + (wid * 16 + rowA) * ASTR + ks * 32 + kofsA);
#pragma unroll
                    for (int nt2 = 0; nt2 < 4; nt2++) {
                        uint32_t b4[4];
                        ldm_x4(b4, bK + (nt2 * 16 + rowB) * ASTR + ks * 32 + kofsB);
                        mma16816h(sc[2 * nt2],     ah, b4[0], b4[1]);
                        mma16816h(sc[2 * nt2 + 1], ah, b4[2], b4[3]);
                    }
                }

                if (kv0 + 63 > q0 + wid * 16) {
                    const int qr = q0 + wid * 16 + (lane >> 2);
#pragma unroll
                    for (int nt = 0; nt < 8; nt++) {
#pragma unroll
                        for (int r = 0; r < 4; r++) {
                            int qrow = qr + ((r >= 2) ? 8 : 0);
                            int kvc  = kv0 + nt * 8 + (lane & 3) * 2 + (r & 1);
                            if (kvc > qrow) sc[nt][r] = -1e30f;
                        }
                    }
                }

#pragma unroll
                for (int rh = 0; rh < 2; rh++) {
                    float mx = -1e30f;
#pragma unroll
                    for (int nt = 0; nt < 8; nt++)
                        mx = fmaxf(mx, fmaxf(sc[nt][rh * 2], sc[nt][rh * 2 + 1]));
                    mx = fmaxf(mx, __shfl_xor_sync(0xffffffffu, mx, 1));
                    mx = fmaxf(mx, __shfl_xor_sync(0xffffffffu, mx, 2));
                    float mn = fmaxf(mrow[rh], mx);
                    float alpha = fexp2(mrow[rh] - mn);
                    mrow[rh] = mn;
                    float sum = 0.0f;
#pragma unroll
                    for (int nt = 0; nt < 8; nt++) {
                        float p0 = fexp2(sc[nt][rh * 2]     - mn);
                        float p1 = fexp2(sc[nt][rh * 2 + 1] - mn);
                        sc[nt][rh * 2]     = p0;
                        sc[nt][rh * 2 + 1] = p1;
                        sum += p0 + p1;
                    }
                    sum += __shfl_xor_sync(0xffffffffu, sum, 1);
                    sum += __shfl_xor_sync(0xffffffffu, sum, 2);
                    lrow[rh] = lrow[rh] * alpha + sum;
#pragma unroll
                    for (int nt = 0; nt < 8; nt++) {
                        oacc[nt][rh * 2]     *= alpha;
                        oacc[nt][rh * 2 + 1] *= alpha;
                    }
                }

                uint32_t ph[4][4];
#pragma unroll
                for (int ks2 = 0; ks2 < 4; ks2++) {
                    const int na = 2 * ks2, nb = 2 * ks2 + 1;
                    __half2 t0 = __floats2half2_rn(sc[na][0], sc[na][1]);
                    __half2 t1 = __floats2half2_rn(sc[na][2], sc[na][3]);
                    __half2 t2 = __floats2half2_rn(sc[nb][0], sc[nb][1]);
                    __half2 t3 = __floats2half2_rn(sc[nb][2], sc[nb][3]);
                    ph[ks2][0] = *(uint32_t*)&t0;
                    ph[ks2][1] = *(uint32_t*)&t1;
                    ph[ks2][2] = *(uint32_t*)&t2;
                    ph[ks2][3] = *(uint32_t*)&t3;
                }

#pragma unroll
                for (int ks2 = 0; ks2 < 4; ks2++) {
#pragma unroll
                    for (int nt2 = 0; nt2 < 4; nt2++) {
                        uint32_t bv[4];
                        uint32_t voff = (ks2 * 16 + (lane & 15)) * ASTR + (nt2 * 16 + (lane >> 4) * 8) * 2;
                        ldm_x4_t(bv, bV + voff);
                        mma16816h(oacc[2 * nt2],     ph[ks2], bv[0], bv[1]);
                        mma16816h(oacc[2 * nt2 + 1], ph[ks2], bv[2], bv[3]);
                    }
                }
            }

            if (jt + 1 < ntiles) {
                __syncthreads();
                if (jt + 2 < ntiles) { loadKV(jt + 2, cur); cp_commit(); cp_wait1(); }
                else cp_wait0();
                __syncthreads();
            }
        }

#pragma unroll
        for (int rh = 0; rh < 2; rh++) {
            float inv = 1.0f / lrow[rh];
            int row = q0 + wid * 16 + (lane >> 2) + rh * 8;
            size_t base = ((size_t)(b * SS + row) * NH + h) * DD;
#pragma unroll
            for (int nt = 0; nt < 8; nt++) {
                float x0 = oacc[nt][rh * 2] * inv;
                float x1 = oacc[nt][rh * 2 + 1] * inv;
                *(__half2*)&ctxh[base + nt * 8 + (lane & 3) * 2] = __floats2half2_rn(x0, x1);
            }
        }
    }
}

// ---------------- host ----------------
extern "C" void kernel_launch(void* const* d_in, const int* in_sizes, int n_in,
                              void* d_out, int out_size)
{
    const float* hidden = (const float*)d_in[0];
    const float* cosT   = (const float*)d_in[1];
    const float* sinT   = (const float*)d_in[2];
    const float* Wq = (const float*)d_in[4];
    const float* Wk = (const float*)d_in[5];
    const float* Wv = (const float*)d_in[6];
    const float* Wo = (const float*)d_in[7];
    float* out = (float*)d_out;

    __half *hid, *w, *ctx, *qh, *kh, *v;
    cudaGetSymbolAddress((void**)&hid, g_hid);
    cudaGetSymbolAddress((void**)&w,   g_w);
    cudaGetSymbolAddress((void**)&ctx, g_ctx);
    cudaGetSymbolAddress((void**)&qh, g_qh);
    cudaGetSymbolAddress((void**)&kh, g_kh);
    cudaGetSymbolAddress((void**)&v,  g_v);

    int ncv = MM * HID / 4 + 4 * (HID * HID / 4);
    convert_all_kernel<<<(ncv + 255) / 256, 256>>>(hidden, Wq, Wk, Wv, Wo, hid, w);

    // QKV projections: dedicated 128x128 kernel, grid (8, 32, 3)
    gemm_qkv_kernel<<<dim3(8, 32, 3), 256>>>(
        hid,
        w + 0 * (size_t)HID * HID, w + 1 * (size_t)HID * HID, w + 2 * (size_t)HID * HID,
        cosT, sinT,
        qh, kh, v);

    cudaFuncSetAttribute(attn_hmma_kernel, cudaFuncAttributeMaxDynamicSharedMemorySize, ATTN_SMEM);
    dim3 aGrid(NQT / 2, NH, BB);
    attn_hmma_kernel<<<aGrid, 256, ATTN_SMEM>>>(qh, kh, v, ctx);

    // Wo projection: dedicated 128x128 kernel (proven R13), grid (8, 32)
    gemm_wo_kernel<<<dim3(8, 32), 256>>>(ctx, w + 3 * (size_t)HID * HID, out);
}